// round 1
// baseline (speedup 1.0000x reference)
#include <cuda_runtime.h>
#include <cuda_bf16.h>

// Problem shape (fixed per metadata): B=32, D=16, H=W=256, N=512.
#define B_ 32
#define D_ 16
#define HW_ 256
#define N_ 512

// Scratch (device globals; no allocations allowed).
// Embeddings stored pre-scaled by 1/sqrt(D) so that:
//   exponent = sq_n + sq_m - 2 * sum_d(a'_d * b'_d)
// g_ebd: [B][N][4] float4  (16 floats per row)
__device__ float4 g_ebd[B_ * N_ * 4];
// g_meta: [B][N] = {sq, mask, tag_as_float, 0}
__device__ float4 g_meta[B_ * N_];
// per-batch scale = 10 / (max(K^2,1) * B)
__device__ float g_scale[B_];

// ---------------------------------------------------------------------------
// Kernel 1: gather embeddings at keypoint pixels, compute sq/mask/tag meta,
// reduce K per batch, write per-batch scale. Also zero the output scalar.
// grid = B_ blocks, 512 threads (one per keypoint).
// ---------------------------------------------------------------------------
__global__ void tagloss_gather_kernel(const float* __restrict__ pred,
                                      const float* __restrict__ kpt,
                                      const int* __restrict__ vis,
                                      const int* __restrict__ tag,
                                      float* __restrict__ out) {
    const int b = blockIdx.x;
    const int n = threadIdx.x;
    const int bn = b * N_ + n;

    // idx = floor(kpt * [W, H]); y = idx[...,0], x = idx[...,1]
    const float k0 = kpt[bn * 2 + 0];
    const float k1 = kpt[bn * 2 + 1];
    const int y = (int)floorf(k0 * (float)HW_);
    const int x = (int)floorf(k1 * (float)HW_);

    // pred[b, d, y, x], stride over d is H*W
    const float* p = pred + ((size_t)b * D_ * HW_ * HW_) + (size_t)y * HW_ + x;
    float e[D_];
    float sq = 0.0f;
#pragma unroll
    for (int d = 0; d < D_; ++d) {
        float v = p[(size_t)d * HW_ * HW_] * 0.25f;  // 1/sqrt(D), D=16
        e[d] = v;
        sq = fmaf(v, v, sq);
    }

    float4* erow = &g_ebd[bn * 4];
#pragma unroll
    for (int j = 0; j < 4; ++j)
        erow[j] = make_float4(e[4 * j + 0], e[4 * j + 1], e[4 * j + 2], e[4 * j + 3]);

    const float maskf = (vis[bn] > 0) ? 1.0f : 0.0f;
    g_meta[bn] = make_float4(sq, maskf, (float)tag[bn], 0.0f);

    // Block reduction of K = sum(mask) over 512 threads.
    __shared__ float red[N_];
    red[n] = maskf;
    __syncthreads();
#pragma unroll
    for (int s = N_ / 2; s > 0; s >>= 1) {
        if (n < s) red[n] += red[n + s];
        __syncthreads();
    }
    if (n == 0) {
        float K = red[0];
        float denom = fmaxf(K * K, 1.0f);
        g_scale[b] = 10.0f / (denom * (float)B_);
        if (b == 0) *out = 0.0f;  // zero the poisoned output before accumulation
    }
}

// ---------------------------------------------------------------------------
// Kernel 2: all-pairs loss.
// grid = (B_, N_/32) = (32, 16) blocks, 256 threads.
// Block handles batch b, rows [tileY*32, tileY*32+32), all 512 columns.
// Thread t: rows r0 = base + (t&15)*2, r0+1 ; columns mq=(t>>4)*32 .. +32.
// Full batch tile (512 rows x 16 floats) + meta staged in 40 KB SMEM.
// ---------------------------------------------------------------------------
__global__ __launch_bounds__(256) void tagloss_pairs_kernel(float* __restrict__ out) {
    __shared__ float4 sE[N_ * 4];   // 32 KB
    __shared__ float4 sM[N_];       // 8 KB

    const int b = blockIdx.x;
    const int t = threadIdx.x;

    // Stage full batch tile: 512 rows, each thread loads 2 rows (4 float4 + meta).
    {
        const float4* ge = &g_ebd[b * N_ * 4];
        const float4* gm = &g_meta[b * N_];
#pragma unroll
        for (int k = 0; k < 2; ++k) {
            int r = t + k * 256;
#pragma unroll
            for (int j = 0; j < 4; ++j) sE[r * 4 + j] = ge[r * 4 + j];
            sM[r] = gm[r];
        }
    }
    __syncthreads();

    const int r0 = blockIdx.y * 32 + (t & 15) * 2;
    const int r1 = r0 + 1;
    const int m0 = (t >> 4) * 32;

    float4 a0[4], a1[4];
#pragma unroll
    for (int j = 0; j < 4; ++j) { a0[j] = sE[r0 * 4 + j]; a1[j] = sE[r1 * 4 + j]; }
    const float4 me0 = sM[r0];
    const float4 me1 = sM[r1];

    float acc0 = 0.0f, acc1 = 0.0f;

#pragma unroll 4
    for (int mi = 0; mi < 32; ++mi) {
        const int m = m0 + mi;
        const float4 mb = sM[m];
        float dot0 = 0.0f, dot1 = 0.0f;
#pragma unroll
        for (int j = 0; j < 4; ++j) {
            const float4 bb = sE[m * 4 + j];
            dot0 = fmaf(a0[j].x, bb.x, dot0);
            dot0 = fmaf(a0[j].y, bb.y, dot0);
            dot0 = fmaf(a0[j].z, bb.z, dot0);
            dot0 = fmaf(a0[j].w, bb.w, dot0);
            dot1 = fmaf(a1[j].x, bb.x, dot1);
            dot1 = fmaf(a1[j].y, bb.y, dot1);
            dot1 = fmaf(a1[j].z, bb.z, dot1);
            dot1 = fmaf(a1[j].w, bb.w, dot1);
        }
        // exponent, pred_sim, true_sim, masked squared error
        float e0 = me0.x + mb.x - 2.0f * dot0;
        float e1 = me1.x + mb.x - 2.0f * dot1;
        float s0 = __fdividef(2.0f, 1.0f + __expf(e0));
        float s1 = __fdividef(2.0f, 1.0f + __expf(e1));
        float t0 = (me0.z == mb.z) ? 1.0f : 0.0f;
        float t1 = (me1.z == mb.z) ? 1.0f : 0.0f;
        float d0 = s0 - t0;
        float d1 = s1 - t1;
        acc0 = fmaf(mb.y, d0 * d0, acc0);
        acc1 = fmaf(mb.y, d1 * d1, acc1);
    }

    float acc = me0.y * acc0 + me1.y * acc1;

    // Block reduction: warp shuffle, then cross-warp via SMEM.
#pragma unroll
    for (int s = 16; s > 0; s >>= 1)
        acc += __shfl_xor_sync(0xFFFFFFFFu, acc, s);

    __shared__ float wsum[8];
    if ((t & 31) == 0) wsum[t >> 5] = acc;
    __syncthreads();
    if (t == 0) {
        float total = 0.0f;
#pragma unroll
        for (int w = 0; w < 8; ++w) total += wsum[w];
        atomicAdd(out, total * g_scale[b]);
    }
}

extern "C" void kernel_launch(void* const* d_in, const int* in_sizes, int n_in,
                              void* d_out, int out_size) {
    const float* pred = (const float*)d_in[0];
    const float* kpt  = (const float*)d_in[1];
    const int*   vis  = (const int*)d_in[2];
    const int*   tag  = (const int*)d_in[3];
    float* out = (float*)d_out;

    tagloss_gather_kernel<<<B_, N_>>>(pred, kpt, vis, tag, out);
    dim3 grid(B_, N_ / 32);
    tagloss_pairs_kernel<<<grid, 256>>>(out);
}

// round 4
// speedup vs baseline: 1.2896x; 1.2896x over previous
#include <cuda_runtime.h>
#include <cuda_bf16.h>

// Problem shape (fixed per metadata): B=32, D=16, H=W=256, N=512.
#define B_ 32
#define D_ 16
#define HW_ 256
#define N_ 512

// Scratch (device globals; no allocations allowed).
// Embeddings stored pre-scaled by 1/sqrt(D) so that:
//   exponent = sq_n + sq_m - 2 * sum_d(a'_d * b'_d)
__device__ float4 g_ebd[B_ * N_ * 4];   // [B][N][4] float4 (16 floats/row)
__device__ float4 g_meta[B_ * N_];      // {sq, mask, tag_as_float, 0}

// ---------------------------------------------------------------------------
// Kernel 1: flat gather — one thread per keypoint, spread across the chip.
// grid = 128 blocks x 128 threads = 16384 = B*N threads.
// ---------------------------------------------------------------------------
__global__ __launch_bounds__(128) void tagloss_gather_kernel(
        const float* __restrict__ pred,
        const float* __restrict__ kpt,
        const int* __restrict__ vis,
        const int* __restrict__ tag,
        float* __restrict__ out) {
    const int bn = blockIdx.x * 128 + threadIdx.x;   // 0 .. B*N-1
    const int b = bn >> 9;

    const float2 k = ((const float2*)kpt)[bn];
    const int y = (int)floorf(k.x * (float)HW_);
    const int x = (int)floorf(k.y * (float)HW_);

    const float* p = pred + ((size_t)b * D_ * HW_ * HW_) + (size_t)y * HW_ + x;
    float e[D_];
    float sq = 0.0f;
#pragma unroll
    for (int d = 0; d < D_; ++d) {
        float v = p[(size_t)d * HW_ * HW_] * 0.25f;  // 1/sqrt(D), D=16
        e[d] = v;
        sq = fmaf(v, v, sq);
    }

    float4* erow = &g_ebd[bn * 4];
#pragma unroll
    for (int j = 0; j < 4; ++j)
        erow[j] = make_float4(e[4 * j + 0], e[4 * j + 1], e[4 * j + 2], e[4 * j + 3]);

    const float maskf = (vis[bn] > 0) ? 1.0f : 0.0f;
    g_meta[bn] = make_float4(sq, maskf, (float)tag[bn], 0.0f);

    if (bn == 0) *out = 0.0f;   // zero the poisoned output before accumulation
}

// ---------------------------------------------------------------------------
// Kernel 2: all-pairs loss, tile-triangular (symmetry: full sum =
//   2 * sum(off-diag upper tiles) + sum(diag tiles); true diagonal is 0).
// grid = (B, 16): block handles batch b, row tile i (32 rows).
// 256 threads = 16 row-pairs (t&15) x 16 column groups (t>>4) of 32 cols.
// Column groups g < i are skipped (weight: g==i -> 1, g>i -> 2).
// Block also computes K = sum(mask) from staged metadata and folds the
// 10 / (max(K^2,1) * B) scale into its atomicAdd.
// ---------------------------------------------------------------------------
__global__ __launch_bounds__(256) void tagloss_pairs_kernel(float* __restrict__ out) {
    __shared__ float4 sE[N_ * 4];   // 32 KB
    __shared__ float4 sM[N_];       // 8 KB
    __shared__ float wsum[8];
    __shared__ float kwsum[8];

    const int b = blockIdx.x;
    const int i = blockIdx.y;
    const int t = threadIdx.x;

    // Stage full batch tile; accumulate per-thread mask sum for K.
    float kp;
    {
        const float4* ge = &g_ebd[b * N_ * 4];
        const float4* gm = &g_meta[b * N_];
        float4 m0, m1;
#pragma unroll
        for (int j = 0; j < 4; ++j) {
            sE[t * 4 + j] = ge[t * 4 + j];
            sE[(t + 256) * 4 + j] = ge[(t + 256) * 4 + j];
        }
        m0 = gm[t];        sM[t] = m0;
        m1 = gm[t + 256];  sM[t + 256] = m1;
        kp = m0.y + m1.y;
    }
    // Warp-reduce K partials, stash per-warp sums.
#pragma unroll
    for (int s = 16; s > 0; s >>= 1)
        kp += __shfl_xor_sync(0xFFFFFFFFu, kp, s);
    if ((t & 31) == 0) kwsum[t >> 5] = kp;
    __syncthreads();

    const int cg = t >> 4;           // this thread's column group
    const int r0 = i * 32 + (t & 15) * 2;
    const int r1 = r0 + 1;

    float acc = 0.0f;
    if (cg >= i) {
        const int m0 = cg * 32;
        float4 a0[4], a1[4];
#pragma unroll
        for (int j = 0; j < 4; ++j) { a0[j] = sE[r0 * 4 + j]; a1[j] = sE[r1 * 4 + j]; }
        const float4 me0 = sM[r0];
        const float4 me1 = sM[r1];

        float acc0 = 0.0f, acc1 = 0.0f;
#pragma unroll 4
        for (int mi = 0; mi < 32; ++mi) {
            const int m = m0 + mi;
            const float4 mb = sM[m];
            float dot0 = 0.0f, dot1 = 0.0f;
#pragma unroll
            for (int j = 0; j < 4; ++j) {
                const float4 bb = sE[m * 4 + j];
                dot0 = fmaf(a0[j].x, bb.x, dot0);
                dot0 = fmaf(a0[j].y, bb.y, dot0);
                dot0 = fmaf(a0[j].z, bb.z, dot0);
                dot0 = fmaf(a0[j].w, bb.w, dot0);
                dot1 = fmaf(a1[j].x, bb.x, dot1);
                dot1 = fmaf(a1[j].y, bb.y, dot1);
                dot1 = fmaf(a1[j].z, bb.z, dot1);
                dot1 = fmaf(a1[j].w, bb.w, dot1);
            }
            float e0 = me0.x + mb.x - 2.0f * dot0;
            float e1 = me1.x + mb.x - 2.0f * dot1;
            float s0 = __fdividef(2.0f, 1.0f + __expf(e0));
            float s1 = __fdividef(2.0f, 1.0f + __expf(e1));
            float t0 = (me0.z == mb.z) ? 1.0f : 0.0f;
            float t1 = (me1.z == mb.z) ? 1.0f : 0.0f;
            float d0 = s0 - t0;
            float d1 = s1 - t1;
            acc0 = fmaf(mb.y, d0 * d0, acc0);
            acc1 = fmaf(mb.y, d1 * d1, acc1);
        }
        const float w = (cg == i) ? 1.0f : 2.0f;   // tile symmetry weight
        acc = (me0.y * acc0 + me1.y * acc1) * w;
    }

    // Block reduction: warp shuffle, then cross-warp via SMEM.
#pragma unroll
    for (int s = 16; s > 0; s >>= 1)
        acc += __shfl_xor_sync(0xFFFFFFFFu, acc, s);
    if ((t & 31) == 0) wsum[t >> 5] = acc;
    __syncthreads();
    if (t == 0) {
        float total = 0.0f, K = 0.0f;
#pragma unroll
        for (int w = 0; w < 8; ++w) { total += wsum[w]; K += kwsum[w]; }
        const float scale = 10.0f / (fmaxf(K * K, 1.0f) * (float)B_);
        atomicAdd(out, total * scale);
    }
}

extern "C" void kernel_launch(void* const* d_in, const int* in_sizes, int n_in,
                              void* d_out, int out_size) {
    const float* pred = (const float*)d_in[0];
    const float* kpt  = (const float*)d_in[1];
    const int*   vis  = (const int*)d_in[2];
    const int*   tag  = (const int*)d_in[3];
    float* out = (float*)d_out;

    tagloss_gather_kernel<<<128, 128>>>(pred, kpt, vis, tag, out);
    dim3 grid(B_, N_ / 32);
    tagloss_pairs_kernel<<<grid, 256>>>(out);
}

// round 5
// speedup vs baseline: 1.8393x; 1.4262x over previous
#include <cuda_runtime.h>
#include <cuda_bf16.h>

// Problem shape (fixed per metadata): B=32, D=16, H=W=256, N=512.
#define B_ 32
#define D_ 16
#define HW_ 256
#define N_ 512

// Scratch (device globals; no allocations allowed).
// Embeddings stored pre-scaled by 1/sqrt(D) so that:
//   exponent = sq_n + sq_m - 2 * sum_d(a'_d * b'_d)
__device__ float4 g_ebd[B_ * N_ * 4];   // [B][N][4] float4 (16 floats/row)
__device__ float4 g_meta[B_ * N_];      // {sq, mask, tag_as_float, 0}

// Upper-triangle job list over 8x8 grid of 64-row tiles (36 jobs/batch).
__constant__ unsigned char JOB_TI[36] = {
    0,0,0,0,0,0,0,0, 1,1,1,1,1,1,1, 2,2,2,2,2,2,
    3,3,3,3,3, 4,4,4,4, 5,5,5, 6,6, 7};
__constant__ unsigned char JOB_TJ[36] = {
    0,1,2,3,4,5,6,7, 1,2,3,4,5,6,7, 2,3,4,5,6,7,
    3,4,5,6,7, 4,5,6,7, 5,6,7, 6,7, 7};

// ---------------------------------------------------------------------------
// Kernel 1: flat gather — one thread per keypoint, spread across the chip.
// ---------------------------------------------------------------------------
__global__ __launch_bounds__(128) void tagloss_gather_kernel(
        const float* __restrict__ pred,
        const float* __restrict__ kpt,
        const int* __restrict__ vis,
        const int* __restrict__ tag,
        float* __restrict__ out) {
    const int bn = blockIdx.x * 128 + threadIdx.x;   // 0 .. B*N-1
    const int b = bn >> 9;

    const float2 k = ((const float2*)kpt)[bn];
    const int y = (int)floorf(k.x * (float)HW_);
    const int x = (int)floorf(k.y * (float)HW_);

    const float* p = pred + ((size_t)b * D_ * HW_ * HW_) + (size_t)y * HW_ + x;
    float e[D_];
    float sq = 0.0f;
#pragma unroll
    for (int d = 0; d < D_; ++d) {
        float v = p[(size_t)d * HW_ * HW_] * 0.25f;  // 1/sqrt(D), D=16
        e[d] = v;
        sq = fmaf(v, v, sq);
    }

    float4* erow = &g_ebd[bn * 4];
#pragma unroll
    for (int j = 0; j < 4; ++j)
        erow[j] = make_float4(e[4 * j + 0], e[4 * j + 1], e[4 * j + 2], e[4 * j + 3]);

    const float maskf = (vis[bn] > 0) ? 1.0f : 0.0f;
    g_meta[bn] = make_float4(sq, maskf, (float)tag[bn], 0.0f);

    if (bn == 0) *out = 0.0f;   // zero the poisoned output before accumulation
}

// ---------------------------------------------------------------------------
// Kernel 2: all-pairs loss, balanced 64x64 tile jobs.
// grid = (B=32, 9). Block (b, jb) runs jobs q = jb*4 .. jb*4+3 (36 total/batch).
// Every block: identical work (4 jobs of 64x64 = 16384 pairs). One wave at
// 2 blocks/SM. Thread: 4 rows (strided by 16) x 4 cols -> 16 pairs/job.
// SMEM rows padded to 5 float4 (80B) -> conflict-free; 5th float4 = row meta.
// ---------------------------------------------------------------------------
__global__ __launch_bounds__(256, 2) void tagloss_pairs_kernel(float* __restrict__ out) {
    __shared__ float4 sE[N_ * 5];   // 40 KB: [row][0..3]=embedding, [4]=meta
    __shared__ float wsum[8];
    __shared__ float kwsum[8];

    const int b = blockIdx.x;
    const int jb = blockIdx.y;
    const int t = threadIdx.x;

    // Stage full batch tile (512 rows); accumulate mask partials for K.
    float kp;
    {
        const float4* ge = &g_ebd[b * N_ * 4];
        const float4* gm = &g_meta[b * N_];
        const int r0 = t, r1 = t + 256;
#pragma unroll
        for (int j = 0; j < 4; ++j) {
            sE[r0 * 5 + j] = ge[r0 * 4 + j];
            sE[r1 * 5 + j] = ge[r1 * 4 + j];
        }
        float4 m0 = gm[r0];
        float4 m1 = gm[r1];
        sE[r0 * 5 + 4] = m0;
        sE[r1 * 5 + 4] = m1;
        kp = m0.y + m1.y;
    }
#pragma unroll
    for (int s = 16; s > 0; s >>= 1)
        kp += __shfl_xor_sync(0xFFFFFFFFu, kp, s);
    if ((t & 31) == 0) kwsum[t >> 5] = kp;
    __syncthreads();

    float accT = 0.0f;

#pragma unroll
    for (int jk = 0; jk < 4; ++jk) {
        const int q = jb * 4 + jk;
        const int ti = JOB_TI[q];
        const int tj = JOB_TJ[q];
        const float w = (ti == tj) ? 1.0f : 2.0f;

        const int rbase = ti * 64 + (t & 15);        // rows strided by 16
        const int cbase = tj * 64 + (t >> 4) * 4;    // 4 consecutive cols

        float4 A[4][4];
        float rsq[4], rtag[4], rmask[4];
#pragma unroll
        for (int rr = 0; rr < 4; ++rr) {
            const int r = rbase + rr * 16;
#pragma unroll
            for (int j = 0; j < 4; ++j) A[rr][j] = sE[r * 5 + j];
            const float4 m = sE[r * 5 + 4];
            rsq[rr] = m.x; rmask[rr] = m.y; rtag[rr] = m.z;
        }

        float acc[4] = {0.0f, 0.0f, 0.0f, 0.0f};
#pragma unroll
        for (int cc = 0; cc < 4; ++cc) {
            const int c = cbase + cc;
            const float4 B0 = sE[c * 5 + 0];
            const float4 B1 = sE[c * 5 + 1];
            const float4 B2 = sE[c * 5 + 2];
            const float4 B3 = sE[c * 5 + 3];
            const float4 cm = sE[c * 5 + 4];
#pragma unroll
            for (int rr = 0; rr < 4; ++rr) {
                // two partial chains for ILP
                float d0, d1;
                d0 = A[rr][0].x * B0.x;
                d1 = A[rr][0].y * B0.y;
                d0 = fmaf(A[rr][0].z, B0.z, d0);
                d1 = fmaf(A[rr][0].w, B0.w, d1);
                d0 = fmaf(A[rr][1].x, B1.x, d0);
                d1 = fmaf(A[rr][1].y, B1.y, d1);
                d0 = fmaf(A[rr][1].z, B1.z, d0);
                d1 = fmaf(A[rr][1].w, B1.w, d1);
                d0 = fmaf(A[rr][2].x, B2.x, d0);
                d1 = fmaf(A[rr][2].y, B2.y, d1);
                d0 = fmaf(A[rr][2].z, B2.z, d0);
                d1 = fmaf(A[rr][2].w, B2.w, d1);
                d0 = fmaf(A[rr][3].x, B3.x, d0);
                d1 = fmaf(A[rr][3].y, B3.y, d1);
                d0 = fmaf(A[rr][3].z, B3.z, d0);
                d1 = fmaf(A[rr][3].w, B3.w, d1);
                const float dot = d0 + d1;
                const float e = fmaf(-2.0f, dot, rsq[rr] + cm.x);
                const float s = __fdividef(2.0f, 1.0f + __expf(e));
                const float tt = (rtag[rr] == cm.z) ? 1.0f : 0.0f;
                const float d = s - tt;
                acc[rr] = fmaf(cm.y, d * d, acc[rr]);
            }
        }
        accT += w * (rmask[0] * acc[0] + rmask[1] * acc[1] +
                     rmask[2] * acc[2] + rmask[3] * acc[3]);
    }

    // Block reduction.
#pragma unroll
    for (int s = 16; s > 0; s >>= 1)
        accT += __shfl_xor_sync(0xFFFFFFFFu, accT, s);
    if ((t & 31) == 0) wsum[t >> 5] = accT;
    __syncthreads();
    if (t == 0) {
        float total = 0.0f, K = 0.0f;
#pragma unroll
        for (int w = 0; w < 8; ++w) { total += wsum[w]; K += kwsum[w]; }
        const float scale = 10.0f / (fmaxf(K * K, 1.0f) * (float)B_);
        atomicAdd(out, total * scale);
    }
}

extern "C" void kernel_launch(void* const* d_in, const int* in_sizes, int n_in,
                              void* d_out, int out_size) {
    const float* pred = (const float*)d_in[0];
    const float* kpt  = (const float*)d_in[1];
    const int*   vis  = (const int*)d_in[2];
    const int*   tag  = (const int*)d_in[3];
    float* out = (float*)d_out;

    tagloss_gather_kernel<<<128, 128>>>(pred, kpt, vis, tag, out);
    dim3 grid(B_, 9);
    tagloss_pairs_kernel<<<grid, 256>>>(out);
}